// round 3
// baseline (speedup 1.0000x reference)
#include <cuda_runtime.h>
#include <math.h>

#define NB   128      // batch
#define NT   32       // time steps
#define DZv  128      // z feature dim
#define DFv  256      // f feature dim
#define LOG2PI_F 1.8378770664093453f

// scratch (no device mallocs allowed)
__device__ float g_Gf[NB * NB];        // logq_f_sum[i][j] (final, incl constants)
__device__ float g_partial[NT * 4];    // per-block partial sums of relu terms

// ---------------------------------------------------------------------------
// Kernel 1: f pairwise log-density matrix.
// grid = 32 blocks (i-chunks of 4), 256 threads.
// smem: As[128][132] (a = exp(-lv) chunk), Bs[128][132] (m*a), Cs[128], Ss[4][260]
// ---------------------------------------------------------------------------
__global__ void k_f(const float* __restrict__ fm,
                    const float* __restrict__ flv,
                    const float* __restrict__ fs) {
    extern __shared__ float sm[];
    float* As = sm;                 // 128*132
    float* Bs = As + 128 * 132;     // 128*132
    float* Cs = Bs + 128 * 132;     // 128
    float* Ss = Cs + 128;           // 4*260

    const int tid = threadIdx.x;
    const int i0  = blockIdx.x * 4;

    // load 4 sample rows (contiguous 1024 floats)
    for (int e = tid; e < 4 * DFv; e += 256) {
        int ii = e >> 8, d = e & 255;
        Ss[ii * 260 + d] = fs[i0 * DFv + e];
    }
    if (tid < 128) Cs[tid] = 0.0f;

    const int ti = tid >> 7;    // 0..1 -> rows {ti, ti+2}
    const int j  = tid & 127;

    float acc0 = 0.0f, acc1 = 0.0f;

    for (int dc = 0; dc < DFv; dc += 128) {
        __syncthreads();
        // stage logvar -> As, mean -> Bs
        for (int e = tid; e < 128 * 128; e += 256) {
            int jj = e >> 7, dd = e & 127;
            As[jj * 132 + dd] = flv[jj * DFv + dc + dd];
            Bs[jj * 132 + dd] = fm[jj * DFv + dc + dd];
        }
        __syncthreads();
        // per-j constant: sum of 2*logvar
        if (tid < 128) {
            float s = 0.0f;
            #pragma unroll 16
            for (int dd = 0; dd < 128; dd++) s += As[tid * 132 + dd];
            Cs[tid] += 2.0f * s;
        }
        __syncthreads();
        // transform in place: As = exp(-lv), Bs = m * exp(-lv)
        for (int e = tid; e < 128 * 128; e += 256) {
            int jj = e >> 7, dd = e & 127;
            int idx = jj * 132 + dd;
            float a = __expf(-As[idx]);
            As[idx] = a;
            Bs[idx] = Bs[idx] * a;
        }
        __syncthreads();
        // accumulate sum((s*a - b)^2)
        #pragma unroll 4
        for (int dd = 0; dd < 128; dd += 4) {
            float4 a4 = *(const float4*)&As[j * 132 + dd];
            float4 b4 = *(const float4*)&Bs[j * 132 + dd];
            float4 s0 = *(const float4*)&Ss[ti * 260 + dc + dd];
            float4 s1 = *(const float4*)&Ss[(ti + 2) * 260 + dc + dd];
            float tA;
            tA = fmaf(s0.x, a4.x, -b4.x); acc0 = fmaf(tA, tA, acc0);
            tA = fmaf(s0.y, a4.y, -b4.y); acc0 = fmaf(tA, tA, acc0);
            tA = fmaf(s0.z, a4.z, -b4.z); acc0 = fmaf(tA, tA, acc0);
            tA = fmaf(s0.w, a4.w, -b4.w); acc0 = fmaf(tA, tA, acc0);
            tA = fmaf(s1.x, a4.x, -b4.x); acc1 = fmaf(tA, tA, acc1);
            tA = fmaf(s1.y, a4.y, -b4.y); acc1 = fmaf(tA, tA, acc1);
            tA = fmaf(s1.z, a4.z, -b4.z); acc1 = fmaf(tA, tA, acc1);
            tA = fmaf(s1.w, a4.w, -b4.w); acc1 = fmaf(tA, tA, acc1);
        }
    }
    __syncthreads();
    const float c = Cs[j] + (float)DFv * LOG2PI_F;
    g_Gf[(i0 + ti)     * NB + j] = -0.5f * (acc0 + c);
    g_Gf[(i0 + ti + 2) * NB + j] = -0.5f * (acc1 + c);
}

// ---------------------------------------------------------------------------
// Kernel 2: z pairwise + all logsumexps + relu terms.
// grid = 128 blocks (t = bid&31, i-chunk of 32 = bid>>5), 256 threads.
// Thread (ti = tid/32, lane): outputs i in {ti+8m}, j in {lane+32k}, m,k in 0..3.
// smem: As[128][132], Bs[128][132], Cs[128], Ss[32][132], Ws[8]
// ---------------------------------------------------------------------------
__global__ void k_z(const float* __restrict__ zm,
                    const float* __restrict__ zlv,
                    const float* __restrict__ zs,
                    const int*   __restrict__ ntp) {
    extern __shared__ float sm[];
    float* As = sm;                  // 128*132
    float* Bs = As + 128 * 132;      // 128*132
    float* Cs = Bs + 128 * 132;      // 128
    float* Ss = Cs + 128;            // 32*132
    float* Ws = Ss + 32 * 132;       // 8

    const int tid  = threadIdx.x;
    const int t    = blockIdx.x & 31;
    const int i0   = (blockIdx.x >> 5) * 32;
    const int lane = tid & 31;
    const int ti   = tid >> 5;       // warp id = row group

    // stage samples for this i-chunk
    for (int e = tid; e < 32 * DZv; e += 256) {
        int ii = e >> 7, d = e & 127;
        Ss[ii * 132 + d] = zs[(i0 + ii) * (NT * DZv) + t * DZv + d];
    }
    // stage logvar -> As, mean -> Bs (all j for this t)
    for (int e = tid; e < 128 * 128; e += 256) {
        int jj = e >> 7, dd = e & 127;
        As[jj * 132 + dd] = zlv[jj * (NT * DZv) + t * DZv + dd];
        Bs[jj * 132 + dd] = zm[jj * (NT * DZv) + t * DZv + dd];
    }
    __syncthreads();
    if (tid < 128) {
        float s = 0.0f;
        #pragma unroll 16
        for (int dd = 0; dd < 128; dd++) s += As[tid * 132 + dd];
        Cs[tid] = 2.0f * s;
    }
    __syncthreads();
    for (int e = tid; e < 128 * 128; e += 256) {
        int jj = e >> 7, dd = e & 127;
        int idx = jj * 132 + dd;
        float a = __expf(-As[idx]);
        As[idx] = a;
        Bs[idx] = Bs[idx] * a;
    }
    __syncthreads();

    float acc[4][4];
    #pragma unroll
    for (int m = 0; m < 4; m++)
        #pragma unroll
        for (int k = 0; k < 4; k++) acc[m][k] = 0.0f;

    for (int d = 0; d < 128; d += 4) {
        float4 s4[4], a4[4], b4[4];
        #pragma unroll
        for (int m = 0; m < 4; m++)
            s4[m] = *(const float4*)&Ss[(ti + 8 * m) * 132 + d];
        #pragma unroll
        for (int k = 0; k < 4; k++) {
            a4[k] = *(const float4*)&As[(lane + 32 * k) * 132 + d];
            b4[k] = *(const float4*)&Bs[(lane + 32 * k) * 132 + d];
        }
        #pragma unroll
        for (int m = 0; m < 4; m++) {
            #pragma unroll
            for (int k = 0; k < 4; k++) {
                float tA;
                tA = fmaf(s4[m].x, a4[k].x, -b4[k].x); acc[m][k] = fmaf(tA, tA, acc[m][k]);
                tA = fmaf(s4[m].y, a4[k].y, -b4[k].y); acc[m][k] = fmaf(tA, tA, acc[m][k]);
                tA = fmaf(s4[m].z, a4[k].z, -b4[k].z); acc[m][k] = fmaf(tA, tA, acc[m][k]);
                tA = fmaf(s4[m].w, a4[k].w, -b4[k].w); acc[m][k] = fmaf(tA, tA, acc[m][k]);
            }
        }
    }

    // epilogue: per-row logsumexps (rows of a group live entirely in one warp)
    const float lognorm = logf(128.0f) + logf((float)ntp[0]);
    float tsum = 0.0f;

    #pragma unroll
    for (int m = 0; m < 4; m++) {
        const int gi = i0 + ti + 8 * m;
        float vz[4], vf[4], vfz[4];
        #pragma unroll
        for (int k = 0; k < 4; k++) {
            int j = lane + 32 * k;
            vz[k]  = -0.5f * (acc[m][k] + Cs[j] + (float)DZv * LOG2PI_F);
            vf[k]  = g_Gf[gi * NB + j];
            vfz[k] = vz[k] + vf[k];
        }
        float Mz  = fmaxf(fmaxf(vz[0],  vz[1]),  fmaxf(vz[2],  vz[3]));
        float Mf  = fmaxf(fmaxf(vf[0],  vf[1]),  fmaxf(vf[2],  vf[3]));
        float Mfz = fmaxf(fmaxf(vfz[0], vfz[1]), fmaxf(vfz[2], vfz[3]));
        #pragma unroll
        for (int o = 16; o > 0; o >>= 1) {
            Mz  = fmaxf(Mz,  __shfl_xor_sync(0xffffffffu, Mz,  o));
            Mf  = fmaxf(Mf,  __shfl_xor_sync(0xffffffffu, Mf,  o));
            Mfz = fmaxf(Mfz, __shfl_xor_sync(0xffffffffu, Mfz, o));
        }
        float Sz  = expf(vz[0]  - Mz)  + expf(vz[1]  - Mz)  + expf(vz[2]  - Mz)  + expf(vz[3]  - Mz);
        float Sf  = expf(vf[0]  - Mf)  + expf(vf[1]  - Mf)  + expf(vf[2]  - Mf)  + expf(vf[3]  - Mf);
        float Sfz = expf(vfz[0] - Mfz) + expf(vfz[1] - Mfz) + expf(vfz[2] - Mfz) + expf(vfz[3] - Mfz);
        #pragma unroll
        for (int o = 16; o > 0; o >>= 1) {
            Sz  += __shfl_xor_sync(0xffffffffu, Sz,  o);
            Sf  += __shfl_xor_sync(0xffffffffu, Sf,  o);
            Sfz += __shfl_xor_sync(0xffffffffu, Sfz, o);
        }
        float lz  = Mz  + logf(Sz);
        float lf  = Mf  + logf(Sf);
        float lfz = Mfz + logf(Sfz);
        float term = lfz - lf - lz + lognorm;   // = logq_fz - logq_f - logq_z
        if (term > 0.0f) tsum += term;
    }

    if (lane == 0) Ws[ti] = tsum;
    __syncthreads();
    if (tid == 0) {
        float s = 0.0f;
        #pragma unroll
        for (int w = 0; w < 8; w++) s += Ws[w];
        g_partial[blockIdx.x] = s;
    }
}

// ---------------------------------------------------------------------------
// Kernel 3: deterministic final reduction.
// ---------------------------------------------------------------------------
__global__ void k_red(float* __restrict__ out) {
    __shared__ float sh[128];
    sh[threadIdx.x] = g_partial[threadIdx.x];
    __syncthreads();
    #pragma unroll
    for (int s = 64; s > 0; s >>= 1) {
        if (threadIdx.x < s) sh[threadIdx.x] += sh[threadIdx.x + s];
        __syncthreads();
    }
    if (threadIdx.x == 0) out[0] = sh[0] * (1.0f / (float)(NT * NB));
}

// ---------------------------------------------------------------------------
extern "C" void kernel_launch(void* const* d_in, const int* in_sizes, int n_in,
                              void* d_out, int out_size) {
    const float* fm  = (const float*)d_in[0];
    const float* flv = (const float*)d_in[1];
    const float* fs  = (const float*)d_in[2];
    const float* zm  = (const float*)d_in[3];
    const float* zlv = (const float*)d_in[4];
    const float* zs  = (const float*)d_in[5];
    const int*   nt  = (const int*)  d_in[6];

    const size_t smem1 = (size_t)(128 * 132 * 2 + 128 + 4 * 260) * sizeof(float);      // ~140 KB
    const size_t smem2 = (size_t)(128 * 132 * 2 + 128 + 32 * 132 + 8) * sizeof(float); // ~149 KB

    cudaFuncSetAttribute(k_f, cudaFuncAttributeMaxDynamicSharedMemorySize, (int)smem1);
    cudaFuncSetAttribute(k_z, cudaFuncAttributeMaxDynamicSharedMemorySize, (int)smem2);

    k_f<<<32, 256, smem1>>>(fm, flv, fs);
    k_z<<<128, 256, smem2>>>(zm, zlv, zs, nt);
    k_red<<<1, 128>>>((float*)d_out);
}

// round 5
// speedup vs baseline: 1.6572x; 1.6572x over previous
#include <cuda_runtime.h>
#include <math.h>

#define NB   128      // batch
#define NT   32       // time steps
#define DZv  128      // z feature dim
#define DFv  256      // f feature dim
#define LOG2PI_F 1.8378770664093453f

typedef unsigned long long ull;

// ----- scratch (__device__ globals; no mallocs allowed) ---------------------
__device__ float g_Gf[NB * NB];          // logq_f_sum[i][j] final
__device__ float g_fa[NB * DFv];         // exp(-f_logvar)
__device__ float g_fb[NB * DFv];         // -f_mean * exp(-f_logvar)
__device__ float g_Cf[NB];               // 2*sum(lv) + DF*log2pi
__device__ float g_za[NB * NT * DZv];    // exp(-z_logvar)   [j][t][d]
__device__ float g_zb[NB * NT * DZv];    // -z_mean * za
__device__ float g_Cz[NT * NB];          // [t][j]: 2*sum(lv) + DZ*log2pi
__device__ float g_partial[NT * 4];

// packed fp32x2 fma (sm_100+ only; ptxas cannot auto-fuse this)
static __device__ __forceinline__ ull fma2(ull a, ull b, ull c) {
    ull d;
    asm("fma.rn.f32x2 %0, %1, %2, %3;" : "=l"(d) : "l"(a), "l"(b), "l"(c));
    return d;
}
static __device__ __forceinline__ float ull_sum2(ull v) {
    union { ull u; float2 f; } w; w.u = v;
    return w.f.x + w.f.y;
}

// ---------------------------------------------------------------------------
// prep_f: grid 128 (one block per f-row j), 256 threads (one per d).
// ---------------------------------------------------------------------------
__global__ void prep_f(const float* __restrict__ fm,
                       const float* __restrict__ flv) {
    __shared__ float red[8];
    const int j = blockIdx.x, d = threadIdx.x;
    const float lv = flv[j * DFv + d];
    const float a  = __expf(-lv);
    g_fa[j * DFv + d] = a;
    g_fb[j * DFv + d] = -fm[j * DFv + d] * a;
    // reduce 2*sum(lv)
    float s = lv;
    #pragma unroll
    for (int o = 16; o > 0; o >>= 1) s += __shfl_xor_sync(0xffffffffu, s, o);
    if ((d & 31) == 0) red[d >> 5] = s;
    __syncthreads();
    if (d == 0) {
        float t = 0.f;
        #pragma unroll
        for (int w = 0; w < 8; w++) t += red[w];
        g_Cf[j] = 2.0f * t + (float)DFv * LOG2PI_F;
    }
}

// ---------------------------------------------------------------------------
// prep_z: grid 4096 (block per (j,t)), 128 threads (one per d).
// ---------------------------------------------------------------------------
__global__ void prep_z(const float* __restrict__ zm,
                       const float* __restrict__ zlv) {
    __shared__ float red[4];
    const int j = blockIdx.x >> 5, t = blockIdx.x & 31, d = threadIdx.x;
    const int idx = j * (NT * DZv) + t * DZv + d;
    const float lv = zlv[idx];
    const float a  = __expf(-lv);
    g_za[idx] = a;
    g_zb[idx] = -zm[idx] * a;
    float s = lv;
    #pragma unroll
    for (int o = 16; o > 0; o >>= 1) s += __shfl_xor_sync(0xffffffffu, s, o);
    if ((d & 31) == 0) red[d >> 5] = s;
    __syncthreads();
    if (d == 0) {
        float tt = red[0] + red[1] + red[2] + red[3];
        g_Cz[t * NB + j] = 2.0f * tt + (float)DZv * LOG2PI_F;
    }
}

// ---------------------------------------------------------------------------
// pair_f: f pairwise matrix. grid (4 i-chunks of 32, 8 j-chunks of 16),
// 256 threads: i = tid&31, jj = tid>>5 handles j0+jj and j0+jj+8.
// smem: st2[128][33] float2 (d-pair major samples), As/Bs[16][260].
// ---------------------------------------------------------------------------
__global__ void pair_f(const float* __restrict__ fs) {
    extern __shared__ float sm[];
    float2* st2 = (float2*)sm;             // 128*33 float2 = 4224 floats
    float*  As  = sm + 128 * 33 * 2;       // 16*260
    float*  Bs  = As + 16 * 260;           // 16*260

    const int tid = threadIdx.x;
    const int i0  = blockIdx.x * 32;
    const int j0  = blockIdx.y * 16;

    // stage samples in d-pair-major layout: st2[d/2][i] = (s[2d], s[2d+1])
    for (int e = tid; e < 32 * DFv; e += 256) {
        int ii = e >> 8, d = e & 255;
        float v = fs[(i0 + ii) * DFv + d];
        ((float*)&st2[(d >> 1) * 33 + ii])[d & 1] = v;
    }
    // stage a/b tiles for 16 j rows
    for (int e = tid; e < 16 * DFv; e += 256) {
        int jj = e >> 8, d = e & 255;
        As[jj * 260 + d] = g_fa[(j0 + jj) * DFv + d];
        Bs[jj * 260 + d] = g_fb[(j0 + jj) * DFv + d];
    }
    __syncthreads();

    const int i  = tid & 31;
    const int jj = tid >> 5;     // 0..7

    ull acc0 = 0ull, acc1 = 0ull;
    const ull* arow0 = (const ull*)&As[jj * 260];
    const ull* brow0 = (const ull*)&Bs[jj * 260];
    const ull* arow1 = (const ull*)&As[(jj + 8) * 260];
    const ull* brow1 = (const ull*)&Bs[(jj + 8) * 260];

    #pragma unroll 4
    for (int dp = 0; dp < DFv / 2; dp++) {
        ull s2 = ((const ull*)st2)[dp * 33 + i];
        ull t0 = fma2(s2, arow0[dp], brow0[dp]);
        acc0 = fma2(t0, t0, acc0);
        ull t1 = fma2(s2, arow1[dp], brow1[dp]);
        acc1 = fma2(t1, t1, acc1);
    }

    g_Gf[(i0 + i) * NB + j0 + jj]     = -0.5f * (ull_sum2(acc0) + g_Cf[j0 + jj]);
    g_Gf[(i0 + i) * NB + j0 + jj + 8] = -0.5f * (ull_sum2(acc1) + g_Cf[j0 + jj + 8]);
}

// ---------------------------------------------------------------------------
// k_z: z pairwise + logsumexps + relu terms.
// grid 128 (t = bid&31, i-chunk = bid>>5), 256 threads.
// Thread (ti=warp, lane): i in {ti+8m}, j in {lane+32k}.
// ---------------------------------------------------------------------------
__global__ void k_z(const float* __restrict__ zs,
                    const int*   __restrict__ ntp) {
    extern __shared__ float sm[];
    float* As = sm;                  // 128*132
    float* Bs = As + 128 * 132;      // 128*132
    float* Ss = Bs + 128 * 132;      // 32*132
    float* Cs = Ss + 32 * 132;       // 128
    float* Ws = Cs + 128;            // 8

    const int tid  = threadIdx.x;
    const int t    = blockIdx.x & 31;
    const int i0   = (blockIdx.x >> 5) * 32;
    const int lane = tid & 31;
    const int ti   = tid >> 5;

    // stage a/b tiles (float4, coalesced)
    for (int e = tid; e < 128 * 32; e += 256) {
        int jj = e >> 5, dq = e & 31;
        *(float4*)&As[jj * 132 + dq * 4] = *(const float4*)&g_za[jj * (NT * DZv) + t * DZv + dq * 4];
        *(float4*)&Bs[jj * 132 + dq * 4] = *(const float4*)&g_zb[jj * (NT * DZv) + t * DZv + dq * 4];
    }
    // stage samples for this i-chunk
    for (int e = tid; e < 32 * 32; e += 256) {
        int ii = e >> 5, dq = e & 31;
        *(float4*)&Ss[ii * 132 + dq * 4] = *(const float4*)&zs[(i0 + ii) * (NT * DZv) + t * DZv + dq * 4];
    }
    if (tid < 128) Cs[tid] = g_Cz[t * NB + tid];
    __syncthreads();

    ull acc[4][4][2];
    #pragma unroll
    for (int m = 0; m < 4; m++)
        #pragma unroll
        for (int k = 0; k < 4; k++) { acc[m][k][0] = 0ull; acc[m][k][1] = 0ull; }

    #pragma unroll 4
    for (int d = 0; d < DZv; d += 4) {
        ulonglong2 s2[4], a2[4], b2[4];
        #pragma unroll
        for (int m = 0; m < 4; m++)
            s2[m] = *(const ulonglong2*)&Ss[(ti + 8 * m) * 132 + d];   // warp-broadcast
        #pragma unroll
        for (int k = 0; k < 4; k++) {
            a2[k] = *(const ulonglong2*)&As[(lane + 32 * k) * 132 + d];
            b2[k] = *(const ulonglong2*)&Bs[(lane + 32 * k) * 132 + d];
        }
        #pragma unroll
        for (int m = 0; m < 4; m++) {
            #pragma unroll
            for (int k = 0; k < 4; k++) {
                ull t0 = fma2(s2[m].x, a2[k].x, b2[k].x);
                acc[m][k][0] = fma2(t0, t0, acc[m][k][0]);
                ull t1 = fma2(s2[m].y, a2[k].y, b2[k].y);
                acc[m][k][1] = fma2(t1, t1, acc[m][k][1]);
            }
        }
    }

    // epilogue: per-row logsumexps (row group lives in one warp)
    const float lognorm = logf(128.0f) + logf((float)ntp[0]);
    float tsum = 0.0f;

    #pragma unroll
    for (int m = 0; m < 4; m++) {
        const int gi = i0 + ti + 8 * m;
        float vz[4], vf[4], vfz[4];
        #pragma unroll
        for (int k = 0; k < 4; k++) {
            int j = lane + 32 * k;
            float a = ull_sum2(acc[m][k][0]) + ull_sum2(acc[m][k][1]);
            vz[k]  = -0.5f * (a + Cs[j]);
            vf[k]  = g_Gf[gi * NB + j];
            vfz[k] = vz[k] + vf[k];
        }
        float Mz  = fmaxf(fmaxf(vz[0],  vz[1]),  fmaxf(vz[2],  vz[3]));
        float Mf  = fmaxf(fmaxf(vf[0],  vf[1]),  fmaxf(vf[2],  vf[3]));
        float Mfz = fmaxf(fmaxf(vfz[0], vfz[1]), fmaxf(vfz[2], vfz[3]));
        #pragma unroll
        for (int o = 16; o > 0; o >>= 1) {
            Mz  = fmaxf(Mz,  __shfl_xor_sync(0xffffffffu, Mz,  o));
            Mf  = fmaxf(Mf,  __shfl_xor_sync(0xffffffffu, Mf,  o));
            Mfz = fmaxf(Mfz, __shfl_xor_sync(0xffffffffu, Mfz, o));
        }
        float Sz  = expf(vz[0]  - Mz)  + expf(vz[1]  - Mz)  + expf(vz[2]  - Mz)  + expf(vz[3]  - Mz);
        float Sf  = expf(vf[0]  - Mf)  + expf(vf[1]  - Mf)  + expf(vf[2]  - Mf)  + expf(vf[3]  - Mf);
        float Sfz = expf(vfz[0] - Mfz) + expf(vfz[1] - Mfz) + expf(vfz[2] - Mfz) + expf(vfz[3] - Mfz);
        #pragma unroll
        for (int o = 16; o > 0; o >>= 1) {
            Sz  += __shfl_xor_sync(0xffffffffu, Sz,  o);
            Sf  += __shfl_xor_sync(0xffffffffu, Sf,  o);
            Sfz += __shfl_xor_sync(0xffffffffu, Sfz, o);
        }
        float term = (Mfz + logf(Sfz)) - (Mf + logf(Sf)) - (Mz + logf(Sz)) + lognorm;
        if (term > 0.0f) tsum += term;
    }

    if (lane == 0) Ws[ti] = tsum;
    __syncthreads();
    if (tid == 0) {
        float s = 0.0f;
        #pragma unroll
        for (int w = 0; w < 8; w++) s += Ws[w];
        g_partial[blockIdx.x] = s;
    }
}

// ---------------------------------------------------------------------------
__global__ void k_red(float* __restrict__ out) {
    __shared__ float sh[128];
    sh[threadIdx.x] = g_partial[threadIdx.x];
    __syncthreads();
    #pragma unroll
    for (int s = 64; s > 0; s >>= 1) {
        if (threadIdx.x < s) sh[threadIdx.x] += sh[threadIdx.x + s];
        __syncthreads();
    }
    if (threadIdx.x == 0) out[0] = sh[0] * (1.0f / (float)(NT * NB));
}

// ---------------------------------------------------------------------------
extern "C" void kernel_launch(void* const* d_in, const int* in_sizes, int n_in,
                              void* d_out, int out_size) {
    const float* fm  = (const float*)d_in[0];
    const float* flv = (const float*)d_in[1];
    const float* fs  = (const float*)d_in[2];
    const float* zm  = (const float*)d_in[3];
    const float* zlv = (const float*)d_in[4];
    const float* zs  = (const float*)d_in[5];
    const int*   nt  = (const int*)  d_in[6];

    const size_t smem_pf = (size_t)(128 * 33 * 2 + 16 * 260 * 2) * sizeof(float);           // ~50 KB
    const size_t smem_kz = (size_t)(128 * 132 * 2 + 32 * 132 + 128 + 8) * sizeof(float);     // ~153 KB

    static int inited = 0;
    if (!inited) {
        cudaFuncSetAttribute(pair_f, cudaFuncAttributeMaxDynamicSharedMemorySize, (int)smem_pf);
        cudaFuncSetAttribute(k_z,    cudaFuncAttributeMaxDynamicSharedMemorySize, (int)smem_kz);
        inited = 1;
    }

    prep_f<<<128, 256>>>(fm, flv);
    prep_z<<<4096, 128>>>(zm, zlv);
    pair_f<<<dim3(4, 8), 256, smem_pf>>>(fs);
    k_z<<<128, 256, smem_kz>>>(zs, nt);
    k_red<<<1, 128>>>((float*)d_out);
}